// round 1
// baseline (speedup 1.0000x reference)
#include <cuda_runtime.h>
#include <math.h>

// ---------------------------------------------------------------------------
// Quantizer: x [4,16,1024] f32, codebook [65536,16] f32.
// out[0:65536] = nearest-codebook-entry per token, laid out [B,D,T];
// out[65536]   = commitment loss (mean squared error) if out_size > 65536.
// ---------------------------------------------------------------------------

#define TOKENS   4096
#define DIM      16
#define NCODES   65536
#define NPAIR    32768
#define CHUNKS   9
#define CPB      3641          // code-pairs per chunk (9*3641 = 32769 >= 32768)
#define TILE_P   256           // pairs per smem tile
#define TILES    15            // tiles per chunk
#define CPB_PAD  (TILE_P*TILES)// 3840 padded pairs per chunk
#define PAIR_F   36            // floats per pair record (32 code + 2 negh + 2 pad)
#define PAIR_U64 18

__device__ float g_cb2[(size_t)CHUNKS * CPB_PAD * PAIR_F];  // ~4.98 MB
__device__ float g_bestv[CHUNKS * TOKENS];
__device__ int   g_besti[CHUNKS * TOKENS];
__device__ float g_err[TOKENS];

__device__ __forceinline__ unsigned long long pack2(float v) {
    unsigned long long r;
    asm("mov.b64 %0, {%1, %1};" : "=l"(r) : "f"(v));
    return r;
}
__device__ __forceinline__ unsigned long long fma2(unsigned long long a,
                                                   unsigned long long b,
                                                   unsigned long long c) {
    unsigned long long d;
    asm("fma.rn.f32x2 %0, %1, %2, %3;" : "=l"(d) : "l"(a), "l"(b), "l"(c));
    return d;
}
__device__ __forceinline__ void unpack2(unsigned long long v, float& lo, float& hi) {
    asm("mov.b64 {%0, %1}, %2;" : "=f"(lo), "=f"(hi) : "l"(v));
}

// ---------------------------------------------------------------------------
// Phase 0: repack codebook into pair-interleaved records with -0.5*||c||^2.
// Record p (36 floats): [c_lo[0],c_hi[0], ..., c_lo[15],c_hi[15], -h_lo,-h_hi, 0,0]
// Padding pairs (beyond real codebook) get -inf bias so they never win argmax.
// ---------------------------------------------------------------------------
__global__ void prep_kernel(const float* __restrict__ cb) {
    int s = blockIdx.x * blockDim.x + threadIdx.x;
    if (s >= CHUNKS * CPB_PAD) return;
    int c   = s / CPB_PAD;
    int off = s - c * CPB_PAD;
    int orig = c * CPB + off;               // original pair index
    float* rec = g_cb2 + (size_t)s * PAIR_F;
    if (off < CPB && orig < NPAIR) {
        const float* a = cb + (size_t)(2 * orig) * DIM;
        const float* b = a + DIM;
        float ha = 0.0f, hb = 0.0f;
#pragma unroll
        for (int d = 0; d < DIM; d++) {
            float va = a[d], vb = b[d];
            rec[2 * d]     = va;
            rec[2 * d + 1] = vb;
            ha = fmaf(va, va, ha);          // sequential, matches ref sum order
            hb = fmaf(vb, vb, hb);
        }
        rec[32] = -0.5f * ha;
        rec[33] = -0.5f * hb;
        rec[34] = 0.0f; rec[35] = 0.0f;
    } else {
        float ninf = __int_as_float(0xff800000);
#pragma unroll
        for (int d = 0; d < 32; d++) rec[d] = 0.0f;
        rec[32] = ninf; rec[33] = ninf;     // never selected
        rec[34] = 0.0f; rec[35] = 0.0f;
    }
}

// ---------------------------------------------------------------------------
// Phase 1: per (token, code-chunk) partial argmax of score = x.c - 0.5*||c||^2
// (equivalent to argmin of squared distance; ||x||^2 is constant per token).
// 256 threads/CTA, one token per thread; codebook streamed via smem tiles.
// ---------------------------------------------------------------------------
__global__ __launch_bounds__(256) void scan_kernel(const float* __restrict__ x) {
    __shared__ float4 s_tile[TILE_P * (PAIR_F / 4)];   // 36 KB

    int token = blockIdx.x * 256 + threadIdx.x;        // grid.x = 16
    int chunk = blockIdx.y;                            // grid.y = 9
    int b = token >> 10;
    int t = token & 1023;

    // x for this token, each dim duplicated into both f32x2 halves
    const float* xb = x + (size_t)b * (DIM * 1024) + t;
    unsigned long long xv[DIM];
#pragma unroll
    for (int d = 0; d < DIM; d++) xv[d] = pack2(xb[d * 1024]);

    float best = __int_as_float(0xff800000);
    int   bi   = 0;

    const float4* src = ((const float4*)g_cb2) +
                        (size_t)chunk * CPB_PAD * (PAIR_F / 4);
    const int codebase = 2 * chunk * CPB;

    for (int tile = 0; tile < TILES; tile++) {
        __syncthreads();
        const float4* ts = src + (size_t)tile * TILE_P * (PAIR_F / 4);
#pragma unroll
        for (int i = 0; i < PAIR_F / 4; i++)
            s_tile[threadIdx.x + i * 256] = ts[threadIdx.x + i * 256];
        __syncthreads();

        const unsigned long long* sp = (const unsigned long long*)s_tile;
        int tilecode = codebase + 2 * tile * TILE_P;

#pragma unroll 4
        for (int p = 0; p < TILE_P; p++) {
            const ulonglong2* r2 =
                (const ulonglong2*)(sp + (size_t)p * PAIR_U64);
            unsigned long long acc =
                ((const unsigned long long*)r2)[16];   // {-h_lo, -h_hi}
#pragma unroll
            for (int j = 0; j < 8; j++) {
                ulonglong2 q = r2[j];
                acc = fma2(q.x, xv[2 * j],     acc);
                acc = fma2(q.y, xv[2 * j + 1], acc);
            }
            float lo, hi;
            unpack2(acc, lo, hi);
            int code = tilecode + 2 * p;
            if (lo > best) { best = lo; bi = code; }      // strict > keeps
            if (hi > best) { best = hi; bi = code + 1; }  // first index (ties)
        }
    }

    g_bestv[chunk * TOKENS + token] = best;
    g_besti[chunk * TOKENS + token] = bi;
}

// ---------------------------------------------------------------------------
// Phase 2: combine chunk partials, gather winning code, write [B,D,T] output,
// compute per-token squared error.
// ---------------------------------------------------------------------------
__global__ __launch_bounds__(256) void finish_kernel(const float* __restrict__ x,
                                                     const float* __restrict__ cb,
                                                     float* __restrict__ out) {
    int token = blockIdx.x * 256 + threadIdx.x;
    int b = token >> 10;
    int t = token & 1023;

    float best = __int_as_float(0xff800000);
    int   bi   = 0;
#pragma unroll
    for (int c = 0; c < CHUNKS; c++) {                 // ascending code ranges:
        float v = g_bestv[c * TOKENS + token];         // strict > keeps lowest
        int   i = g_besti[c * TOKENS + token];         // index on ties
        if (v > best) { best = v; bi = i; }
    }

    const float* q = cb + (size_t)bi * DIM;
    float err = 0.0f;
#pragma unroll
    for (int d = 0; d < DIM; d++) {
        float qd = q[d];
        float xd = x[(size_t)b * (DIM * 1024) + d * 1024 + t];
        float df = qd - xd;
        err = fmaf(df, df, err);
        out[(size_t)b * (DIM * 1024) + d * 1024 + t] = qd;
    }
    g_err[token] = err;
}

// ---------------------------------------------------------------------------
// Phase 3: deterministic reduction of per-token errors -> loss.
// ---------------------------------------------------------------------------
__global__ __launch_bounds__(1024) void loss_kernel(float* __restrict__ out,
                                                    int out_size) {
    __shared__ float s[1024];
    int tid = threadIdx.x;
    float v = 0.0f;
#pragma unroll
    for (int i = 0; i < TOKENS / 1024; i++)
        v += g_err[tid * (TOKENS / 1024) + i];
    s[tid] = v;
    __syncthreads();
    for (int stride = 512; stride > 0; stride >>= 1) {
        if (tid < stride) s[tid] += s[tid + stride];
        __syncthreads();
    }
    if (tid == 0 && out_size > NCODES)
        out[NCODES] = s[0] / (float)(TOKENS * DIM);
}

// ---------------------------------------------------------------------------
extern "C" void kernel_launch(void* const* d_in, const int* in_sizes, int n_in,
                              void* d_out, int out_size) {
    const float* x  = (const float*)d_in[0];   // [4,16,1024]
    const float* cb = (const float*)d_in[1];   // [65536,16]
    float* out = (float*)d_out;

    prep_kernel<<<(CHUNKS * CPB_PAD + 255) / 256, 256>>>(cb);

    dim3 grid1(TOKENS / 256, CHUNKS);
    scan_kernel<<<grid1, 256>>>(x);

    finish_kernel<<<TOKENS / 256, 256>>>(x, cb, out);

    loss_kernel<<<1, 1024>>>(out, out_size);
}

// round 2
// speedup vs baseline: 1.0487x; 1.0487x over previous
#include <cuda_runtime.h>
#include <math.h>

// ---------------------------------------------------------------------------
// Quantizer: x [4,16,1024] f32, codebook [65536,16] f32.
// out[0:65536] = nearest codebook entry per token, laid out [B,D,T];
// out[65536]   = commitment loss (MSE) if out_size > 65536.
// Score trick: argmin ||x-c||^2 == argmax (x.c - 0.5||c||^2).
// ---------------------------------------------------------------------------

#define TOKENS   4096
#define DIM      16
#define NCODES   65536
#define NPAIR    32768
#define CHUNKS   18
#define CPB      1821          // code-pairs per chunk (18*1821 = 32778 >= 32768)
#define TILE_P   128           // pairs per smem tile
#define TILES    16            // tiles per chunk
#define CPB_PAD  (TILE_P*TILES)   // 2048 padded pairs per chunk
#define PAIR_F   36            // floats per record (32 code + 2 negh + 2 pad)
#define PAIR_U64 18
#define TILE_F4  (TILE_P * (PAIR_F/4))   // 1152 float4 per tile

__device__ float g_cb2[(size_t)CHUNKS * CPB_PAD * PAIR_F];  // ~5.3 MB
__device__ float g_bestv[CHUNKS * TOKENS];
__device__ int   g_besti[CHUNKS * TOKENS];
__device__ float g_err[TOKENS];

__device__ __forceinline__ unsigned long long pack2(float v) {
    unsigned long long r;
    asm("mov.b64 %0, {%1, %1};" : "=l"(r) : "f"(v));
    return r;
}
__device__ __forceinline__ unsigned long long fma2(unsigned long long a,
                                                   unsigned long long b,
                                                   unsigned long long c) {
    unsigned long long d;
    asm("fma.rn.f32x2 %0, %1, %2, %3;" : "=l"(d) : "l"(a), "l"(b), "l"(c));
    return d;
}
__device__ __forceinline__ void unpack2(unsigned long long v, float& lo, float& hi) {
    asm("mov.b64 {%0, %1}, %2;" : "=f"(lo), "=f"(hi) : "l"(v));
}
__device__ __forceinline__ void cpasync16(void* dst_smem, const void* src) {
    unsigned saddr = (unsigned)__cvta_generic_to_shared(dst_smem);
    asm volatile("cp.async.cg.shared.global [%0], [%1], 16;"
                 :: "r"(saddr), "l"(src));
}

// ---------------------------------------------------------------------------
// Phase 0: repack codebook into pair-interleaved records with -0.5*||c||^2.
// Record p (36 floats): [c_lo[0],c_hi[0],...,c_lo[15],c_hi[15], -h_lo,-h_hi, 0,0]
// Padding pairs get -inf bias so they never win the argmax.
// ---------------------------------------------------------------------------
__global__ void prep_kernel(const float* __restrict__ cb) {
    int s = blockIdx.x * blockDim.x + threadIdx.x;
    if (s >= CHUNKS * CPB_PAD) return;
    int c   = s / CPB_PAD;
    int off = s - c * CPB_PAD;
    int orig = c * CPB + off;               // original pair index
    float* rec = g_cb2 + (size_t)s * PAIR_F;
    if (off < CPB && orig < NPAIR) {
        const float* a = cb + (size_t)(2 * orig) * DIM;
        const float* b = a + DIM;
        float ha = 0.0f, hb = 0.0f;
#pragma unroll
        for (int d = 0; d < DIM; d++) {
            float va = a[d], vb = b[d];
            rec[2 * d]     = va;
            rec[2 * d + 1] = vb;
            ha = fmaf(va, va, ha);
            hb = fmaf(vb, vb, hb);
        }
        rec[32] = -0.5f * ha;
        rec[33] = -0.5f * hb;
        rec[34] = 0.0f; rec[35] = 0.0f;
    } else {
        float ninf = __int_as_float(0xff800000);
#pragma unroll
        for (int d = 0; d < 32; d++) rec[d] = 0.0f;
        rec[32] = ninf; rec[33] = ninf;
        rec[34] = 0.0f; rec[35] = 0.0f;
    }
}

// ---------------------------------------------------------------------------
// Phase 1: per (token, chunk) partial argmax, double-buffered smem pipeline.
// grid (16, 18), 256 threads, 2 CTAs/SM.
// ---------------------------------------------------------------------------
__global__ __launch_bounds__(256, 2) void scan_kernel(const float* __restrict__ x) {
    __shared__ float4 s_buf[2][TILE_F4];   // 2 x 18 KB

    const int token = blockIdx.x * 256 + threadIdx.x;  // grid.x = 16
    const int chunk = blockIdx.y;                      // grid.y = 18
    const int b = token >> 10;
    const int t = token & 1023;

    // x for this token, each dim duplicated into both f32x2 halves
    const float* xb = x + (size_t)b * (DIM * 1024) + t;
    unsigned long long xv[DIM];
#pragma unroll
    for (int d = 0; d < DIM; d++) xv[d] = pack2(xb[d * 1024]);

    float best = __int_as_float(0xff800000);
    int   bi   = 0;

    const float4* src = ((const float4*)g_cb2) +
                        (size_t)chunk * CPB_PAD * (PAIR_F / 4);
    const int codebase = 2 * chunk * CPB;

    // prefetch tile 0
#pragma unroll
    for (int i = threadIdx.x; i < TILE_F4; i += 256)
        cpasync16(&s_buf[0][i], &src[i]);
    asm volatile("cp.async.commit_group;");

    for (int tile = 0; tile < TILES; tile++) {
        if (tile + 1 < TILES) {
            const float4* ns = src + (size_t)(tile + 1) * TILE_F4;
            float4* nb = s_buf[(tile + 1) & 1];
#pragma unroll
            for (int i = threadIdx.x; i < TILE_F4; i += 256)
                cpasync16(&nb[i], &ns[i]);
            asm volatile("cp.async.commit_group;");
            asm volatile("cp.async.wait_group 1;");
        } else {
            asm volatile("cp.async.wait_group 0;");
        }
        __syncthreads();

        const unsigned long long* sp =
            (const unsigned long long*)s_buf[tile & 1];
        const int tilecode = codebase + 2 * tile * TILE_P;

#pragma unroll 4
        for (int p = 0; p < TILE_P; p++) {
            const ulonglong2* r2 = (const ulonglong2*)(sp + (size_t)p * PAIR_U64);
            unsigned long long acc = sp[(size_t)p * PAIR_U64 + 16]; // {-h_lo,-h_hi}
#pragma unroll
            for (int j = 0; j < 8; j++) {
                ulonglong2 q = r2[j];
                acc = fma2(q.x, xv[2 * j],     acc);
                acc = fma2(q.y, xv[2 * j + 1], acc);
            }
            float lo, hi;
            unpack2(acc, lo, hi);
            float m = fmaxf(lo, hi);
            int idx = tilecode + 2 * p + ((hi > lo) ? 1 : 0); // ties -> lo (lower idx)
            if (m > best) { best = m; bi = idx; }             // ties -> earlier idx
        }
        __syncthreads();
    }

    g_bestv[chunk * TOKENS + token] = best;
    g_besti[chunk * TOKENS + token] = bi;
}

// ---------------------------------------------------------------------------
// Phase 2: combine chunk partials, gather winning code, write [B,D,T] output,
// per-token squared error.
// ---------------------------------------------------------------------------
__global__ __launch_bounds__(256) void finish_kernel(const float* __restrict__ x,
                                                     const float* __restrict__ cb,
                                                     float* __restrict__ out) {
    int token = blockIdx.x * 256 + threadIdx.x;
    int b = token >> 10;
    int t = token & 1023;

    float best = __int_as_float(0xff800000);
    int   bi   = 0;
#pragma unroll
    for (int c = 0; c < CHUNKS; c++) {             // ascending code ranges:
        float v = g_bestv[c * TOKENS + token];     // strict > keeps lowest
        int   i = g_besti[c * TOKENS + token];     // index on ties
        if (v > best) { best = v; bi = i; }
    }

    const float* q = cb + (size_t)bi * DIM;
    float err = 0.0f;
#pragma unroll
    for (int d = 0; d < DIM; d++) {
        float qd = q[d];
        float xd = x[(size_t)b * (DIM * 1024) + d * 1024 + t];
        float df = qd - xd;
        err = fmaf(df, df, err);
        out[(size_t)b * (DIM * 1024) + d * 1024 + t] = qd;
    }
    g_err[token] = err;
}

// ---------------------------------------------------------------------------
// Phase 3: deterministic reduction of per-token errors -> loss.
// ---------------------------------------------------------------------------
__global__ __launch_bounds__(1024) void loss_kernel(float* __restrict__ out,
                                                    int out_size) {
    __shared__ float s[1024];
    int tid = threadIdx.x;
    float v = 0.0f;
#pragma unroll
    for (int i = 0; i < TOKENS / 1024; i++)
        v += g_err[tid * (TOKENS / 1024) + i];
    s[tid] = v;
    __syncthreads();
    for (int stride = 512; stride > 0; stride >>= 1) {
        if (tid < stride) s[tid] += s[tid + stride];
        __syncthreads();
    }
    if (tid == 0 && out_size > NCODES)
        out[NCODES] = s[0] / (float)(TOKENS * DIM);
}

// ---------------------------------------------------------------------------
extern "C" void kernel_launch(void* const* d_in, const int* in_sizes, int n_in,
                              void* d_out, int out_size) {
    const float* x  = (const float*)d_in[0];   // [4,16,1024]
    const float* cb = (const float*)d_in[1];   // [65536,16]
    float* out = (float*)d_out;

    prep_kernel<<<(CHUNKS * CPB_PAD + 255) / 256, 256>>>(cb);

    dim3 grid1(TOKENS / 256, CHUNKS);
    scan_kernel<<<grid1, 256>>>(x);

    finish_kernel<<<TOKENS / 256, 256>>>(x, cb, out);

    loss_kernel<<<1, 1024>>>(out, out_size);
}